// round 1
// baseline (speedup 1.0000x reference)
#include <cuda_runtime.h>
#include <math.h>
#include <stdint.h>

// Problem constants
#define NB   128
#define TT   30
#define TCAP 31
#define CIN  1280
#define WD   512
#define HD   1024
#define VO   10000
#define G4   4096
#define K2   2048

// ---------------- device scratch (allocation-free) ----------------
__device__ float g_imgT[2048 * CIN];            // (n*16+p, c)          10.5 MB
__device__ float g_A2[2048 * HD];               // (n*16+p, h)           8.4 MB
__device__ float g_hcat[NB * K2];               // [n][0:1024)=h, [1024:2048)=attn
__device__ float g_c[NB * HD];
__device__ float g_Wcat[K2 * G4];               // rows 0..1023 = Wh, 1024..2047 = Wattn
__device__ float g_xemb[NB * TT * WD];
__device__ float g_xpre[NB * TT * G4];          // x@Wx + b, (n, t, 4096)
__device__ float g_a[NB * G4];
__device__ float g_hs[NB * TT * HD];            // (n*30+t, h)
__device__ float g_logits[(size_t)NB * TT * VO];// 153.6 MB
__device__ float g_rowloss[NB * TT];

// ---------------- generic tiled SGEMM: C = A@B (+bias) (+Cin) ----------------
// A: M x K row-major (lda), B: K x N row-major (ldb).
// Requires: M % BM == 0, K % BK == 0, lda/ldb/ldcin/ldc % 4 == 0. N edge guarded.
template<int BM, int BN, int BK, int TM, int TN>
__global__ void gemm_k(int M, int N, int K,
                       const float* __restrict__ A, int lda,
                       const float* __restrict__ B, int ldb,
                       const float* __restrict__ bias,
                       const float* __restrict__ Cin, int ldcin,
                       float* __restrict__ C, int ldc)
{
    constexpr int TX = BN / TN;
    constexpr int TY = BM / TM;
    constexpr int NT = TX * TY;

    __shared__ __align__(16) float As[BK][BM];
    __shared__ __align__(16) float Bs[BK][BN];

    const int bm0 = blockIdx.y * BM;
    const int bn0 = blockIdx.x * BN;
    const int tid = threadIdx.x;
    const int tx  = tid % TX;
    const int ty  = tid / TX;

    float acc[TM][TN];
#pragma unroll
    for (int i = 0; i < TM; i++)
#pragma unroll
        for (int j = 0; j < TN; j++) acc[i][j] = 0.f;

    for (int k0 = 0; k0 < K; k0 += BK) {
        // A tile (BM x BK), float4 loads, transpose into As[kk][m]
        constexpr int A4 = BM * BK / 4;
        for (int i = tid; i < A4; i += NT) {
            int idx = i * 4;
            int m  = idx / BK;
            int kk = idx % BK;
            float4 v = *reinterpret_cast<const float4*>(
                &A[(size_t)(bm0 + m) * lda + k0 + kk]);
            As[kk + 0][m] = v.x;
            As[kk + 1][m] = v.y;
            As[kk + 2][m] = v.z;
            As[kk + 3][m] = v.w;
        }
        // B tile (BK x BN)
        constexpr int B4 = BK * BN / 4;
        for (int i = tid; i < B4; i += NT) {
            int idx = i * 4;
            int kk = idx / BN;
            int nn = idx % BN;
            int col = bn0 + nn;
            float4 v;
            if (col + 3 < N) {
                v = *reinterpret_cast<const float4*>(
                    &B[(size_t)(k0 + kk) * ldb + col]);
            } else {
                v.x = (col + 0 < N) ? B[(size_t)(k0 + kk) * ldb + col + 0] : 0.f;
                v.y = (col + 1 < N) ? B[(size_t)(k0 + kk) * ldb + col + 1] : 0.f;
                v.z = (col + 2 < N) ? B[(size_t)(k0 + kk) * ldb + col + 2] : 0.f;
                v.w = (col + 3 < N) ? B[(size_t)(k0 + kk) * ldb + col + 3] : 0.f;
            }
            *reinterpret_cast<float4*>(&Bs[kk][nn]) = v;
        }
        __syncthreads();

#pragma unroll
        for (int kk = 0; kk < BK; kk++) {
            float ra[TM], rb[TN];
#pragma unroll
            for (int i = 0; i < TM; i += 4) {
                float4 v = *reinterpret_cast<const float4*>(&As[kk][ty * TM + i]);
                ra[i] = v.x; ra[i + 1] = v.y; ra[i + 2] = v.z; ra[i + 3] = v.w;
            }
#pragma unroll
            for (int j = 0; j < TN; j += 4) {
                float4 v = *reinterpret_cast<const float4*>(&Bs[kk][tx * TN + j]);
                rb[j] = v.x; rb[j + 1] = v.y; rb[j + 2] = v.z; rb[j + 3] = v.w;
            }
#pragma unroll
            for (int i = 0; i < TM; i++)
#pragma unroll
                for (int j = 0; j < TN; j++)
                    acc[i][j] += ra[i] * rb[j];
        }
        __syncthreads();
    }

#pragma unroll
    for (int i = 0; i < TM; i++) {
        int m = bm0 + ty * TM + i;
#pragma unroll
        for (int j = 0; j < TN; j++) {
            int n = bn0 + tx * TN + j;
            if (n < N) {
                float v = acc[i][j];
                if (bias) v += bias[n];
                if (Cin)  v += Cin[(size_t)m * ldcin + n];
                C[(size_t)m * ldc + n] = v;
            }
        }
    }
}

// ---------------- small kernels ----------------
__global__ void transpose_images_k(const float* __restrict__ images)
{
    int idx = blockIdx.x * blockDim.x + threadIdx.x;
    if (idx >= 2048 * CIN) return;
    int m = idx / CIN;      // n*16 + p
    int c = idx % CIN;
    int n = m >> 4;
    int p = m & 15;
    g_imgT[idx] = images[((size_t)n * CIN + c) * 16 + p];
}

__global__ void h0_k()
{
    int idx = blockIdx.x * blockDim.x + threadIdx.x;
    if (idx >= NB * HD) return;
    int n = idx / HD;
    int h = idx % HD;
    float s = 0.f;
#pragma unroll
    for (int p = 0; p < 16; p++)
        s += g_A2[((size_t)n * 16 + p) * HD + h];
    s *= (1.f / 16.f);
    g_hcat[n * K2 + h] = s;
    g_c[idx] = s;
}

__global__ void build_wcat_k(const float* __restrict__ Wh,
                             const float* __restrict__ Wattn)
{
    int idx = blockIdx.x * blockDim.x + threadIdx.x;
    if (idx >= K2 * G4) return;
    int r = idx / G4;
    int j = idx % G4;
    g_Wcat[idx] = (r < HD) ? Wh[(size_t)r * G4 + j]
                           : Wattn[(size_t)(r - HD) * G4 + j];
}

__global__ void embed_k(const int* __restrict__ caps,
                        const float* __restrict__ W_embed)
{
    int idx = blockIdx.x * blockDim.x + threadIdx.x;
    if (idx >= NB * TT * WD) return;
    int row = idx / WD;
    int d   = idx % WD;
    int n = row / TT;
    int t = row % TT;
    int tok = caps[n * TCAP + t];
    g_xemb[idx] = W_embed[(size_t)tok * WD + d];
}

// per-batch attention: scores -> softmax(16) -> attn, writes g_hcat[:,1024:2048]
__global__ void attn_k()
{
    const int n = blockIdx.x;
    const float* __restrict__ h  = g_hcat + (size_t)n * K2;
    const float* __restrict__ An = g_A2 + (size_t)n * 16 * HD;

    __shared__ float sc[16];
    __shared__ float w[16];

    int wid  = threadIdx.x >> 5;   // 16 warps
    int lane = threadIdx.x & 31;

    float s = 0.f;
    for (int hh = lane; hh < HD; hh += 32)
        s += h[hh] * An[wid * HD + hh];
#pragma unroll
    for (int o = 16; o; o >>= 1)
        s += __shfl_xor_sync(0xFFFFFFFFu, s, o);
    if (lane == 0) sc[wid] = s * 0.03125f;   // 1/sqrt(1024)
    __syncthreads();

    if (threadIdx.x == 0) {
        float mx = sc[0];
#pragma unroll
        for (int p = 1; p < 16; p++) mx = fmaxf(mx, sc[p]);
        float se = 0.f;
#pragma unroll
        for (int p = 0; p < 16; p++) { float e = expf(sc[p] - mx); w[p] = e; se += e; }
        float inv = 1.f / se;
#pragma unroll
        for (int p = 0; p < 16; p++) w[p] *= inv;
    }
    __syncthreads();

    for (int hh = threadIdx.x; hh < HD; hh += 512) {
        float acc = 0.f;
#pragma unroll
        for (int p = 0; p < 16; p++)
            acc += w[p] * An[p * HD + hh];
        g_hcat[(size_t)n * K2 + HD + hh] = acc;
    }
}

__device__ __forceinline__ float sigf(float x) { return 1.f / (1.f + expf(-x)); }

__global__ void lstm_k(int t)
{
    int idx = blockIdx.x * blockDim.x + threadIdx.x;
    if (idx >= NB * HD) return;
    int n = idx / HD;
    int h = idx % HD;
    const float* an = g_a + (size_t)n * G4;
    float i_ = an[h];
    float f_ = an[HD + h];
    float o_ = an[2 * HD + h];
    float gg = an[3 * HD + h];
    float cp = g_c[idx];
    float cn = sigf(f_) * cp + sigf(i_) * tanhf(gg);
    float hn = sigf(o_) * tanhf(cn);
    g_c[idx] = cn;
    g_hcat[(size_t)n * K2 + h] = hn;
    g_hs[((size_t)n * TT + t) * HD + h] = hn;
}

__global__ void loss_row_k(const int* __restrict__ caps)
{
    const int r = blockIdx.x;
    const int n = r / TT;
    const int t = r % TT;
    const int tgt = caps[n * TCAP + t + 1];
    const float* __restrict__ L = g_logits + (size_t)r * VO;

    __shared__ float red[256];
    const int tid = threadIdx.x;

    float mx = -1e30f;
    for (int j = tid; j < VO; j += 256) mx = fmaxf(mx, L[j]);
    red[tid] = mx; __syncthreads();
    for (int s = 128; s; s >>= 1) {
        if (tid < s) red[tid] = fmaxf(red[tid], red[tid + s]);
        __syncthreads();
    }
    mx = red[0]; __syncthreads();

    float se = 0.f;
    for (int j = tid; j < VO; j += 256) se += expf(L[j] - mx);
    red[tid] = se; __syncthreads();
    for (int s = 128; s; s >>= 1) {
        if (tid < s) red[tid] += red[tid + s];
        __syncthreads();
    }
    if (tid == 0) {
        float lse = mx + logf(red[0]);
        float nll = lse - L[tgt];
        g_rowloss[r] = (tgt != 0) ? nll : 0.f;
    }
}

__global__ void final_k(float* __restrict__ out)
{
    __shared__ float red[256];
    const int tid = threadIdx.x;
    float s = 0.f;
    for (int r = tid; r < NB * TT; r += 256) s += g_rowloss[r];
    red[tid] = s; __syncthreads();
    for (int st = 128; st; st >>= 1) {
        if (tid < st) red[tid] += red[tid + st];
        __syncthreads();
    }
    if (tid == 0) out[0] = red[0] / (float)NB;
}

// ---------------- launch ----------------
extern "C" void kernel_launch(void* const* d_in, const int* in_sizes, int n_in,
                              void* d_out, int out_size)
{
    const float* images  = (const float*)d_in[0];
    const int*   caps    = (const int*)  d_in[1];
    const float* W_embed = (const float*)d_in[2];
    const float* W_proj  = (const float*)d_in[3];
    const float* b_proj  = (const float*)d_in[4];
    const float* Wx      = (const float*)d_in[5];
    const float* Wh      = (const float*)d_in[6];
    const float* Wattn   = (const float*)d_in[7];
    const float* b       = (const float*)d_in[8];
    const float* W_vocab = (const float*)d_in[9];
    const float* b_vocab = (const float*)d_in[10];
    float* out = (float*)d_out;

    static float *p_imgT = nullptr, *p_A2, *p_hcat, *p_Wcat, *p_xemb,
                 *p_xpre, *p_a, *p_hs, *p_logits;
    if (!p_imgT) {
        cudaGetSymbolAddress((void**)&p_imgT,   g_imgT);
        cudaGetSymbolAddress((void**)&p_A2,     g_A2);
        cudaGetSymbolAddress((void**)&p_hcat,   g_hcat);
        cudaGetSymbolAddress((void**)&p_Wcat,   g_Wcat);
        cudaGetSymbolAddress((void**)&p_xemb,   g_xemb);
        cudaGetSymbolAddress((void**)&p_xpre,   g_xpre);
        cudaGetSymbolAddress((void**)&p_a,      g_a);
        cudaGetSymbolAddress((void**)&p_hs,     g_hs);
        cudaGetSymbolAddress((void**)&p_logits, g_logits);
    }

    // 1. transpose images -> (n*16+p, c)
    transpose_images_k<<<(2048 * CIN + 255) / 256, 256>>>(images);

    // 2. projection: A2 (2048 x 1024) = imgT @ W_proj + b_proj
    gemm_k<128, 128, 16, 8, 8><<<dim3(HD / 128, 2048 / 128), 256>>>(
        2048, HD, CIN, p_imgT, CIN, W_proj, HD, b_proj, nullptr, 0, p_A2, HD);

    // 3. h0 = mean over pixels; init h (into hcat) and c
    h0_k<<<(NB * HD + 255) / 256, 256>>>();

    // 4. Wcat = [Wh ; Wattn]
    build_wcat_k<<<(K2 * G4 + 255) / 256, 256>>>(Wh, Wattn);

    // 5. embedding gather
    embed_k<<<(NB * TT * WD + 255) / 256, 256>>>(caps, W_embed);

    // 6. x_pre = x_emb @ Wx + b  (bias b folded in here, once)
    gemm_k<128, 128, 16, 8, 8><<<dim3(G4 / 128, (NB * TT) / 128), 256>>>(
        NB * TT, G4, WD, p_xemb, WD, Wx, G4, b, nullptr, 0, p_xpre, G4);

    // 7. recurrent loop
    for (int t = 0; t < TT; t++) {
        attn_k<<<NB, 512>>>();
        gemm_k<64, 64, 16, 4, 4><<<dim3(G4 / 64, NB / 64), 256>>>(
            NB, G4, K2, p_hcat, K2, p_Wcat, G4,
            nullptr, p_xpre + (size_t)t * G4, TT * G4, p_a, G4);
        lstm_k<<<(NB * HD + 255) / 256, 256>>>(t);
    }

    // 8. logits = hs @ W_vocab + b_vocab
    gemm_k<128, 128, 16, 8, 8><<<dim3((VO + 127) / 128, (NB * TT) / 128), 256>>>(
        NB * TT, VO, HD, p_hs, HD, W_vocab, VO, b_vocab, nullptr, 0, p_logits, VO);

    // 9. per-row logsumexp + masked NLL
    loss_row_k<<<NB * TT, 256>>>(caps);

    // 10. final masked mean
    final_k<<<1, 256>>>(out);
}

// round 2
// speedup vs baseline: 1.1799x; 1.1799x over previous
#include <cuda_runtime.h>
#include <math.h>
#include <stdint.h>

// Problem constants
#define NB   128
#define TT   30
#define TCAP 31
#define CIN  1280
#define WD   512
#define HD   1024
#define VO   10000
#define G4   4096
#define K2   2048

// ---------------- device scratch (allocation-free) ----------------
__device__ float g_imgT[2048 * CIN];
__device__ float g_A2[2048 * HD];
__device__ float g_hcat[NB * K2];               // [n][0:1024)=h, [1024:2048)=attn
__device__ float g_c[NB * HD];
__device__ float g_Wcat[K2 * G4];               // rows 0..1023 = Wh, 1024..2047 = Wattn
__device__ float g_xemb[NB * TT * WD];
__device__ float g_xpre[NB * TT * G4];
__device__ float g_a[NB * G4];
__device__ float g_hs[NB * TT * HD];
__device__ float g_logits[(size_t)NB * TT * VO];
__device__ float g_rowloss[NB * TT];

// ---------------- tf32 helpers ----------------
__device__ __forceinline__ uint32_t f2tf(float f) {
    uint32_t u;
    asm("cvt.rna.tf32.f32 %0, %1;" : "=r"(u) : "f"(f));
    return u;
}

__device__ __forceinline__ void mma_tf32(float c[4], const uint32_t a[4], const uint32_t b[2]) {
    asm volatile(
        "mma.sync.aligned.m16n8k8.row.col.f32.tf32.tf32.f32 "
        "{%0,%1,%2,%3}, {%4,%5,%6,%7}, {%8,%9}, {%0,%1,%2,%3};\n"
        : "+f"(c[0]), "+f"(c[1]), "+f"(c[2]), "+f"(c[3])
        : "r"(a[0]), "r"(a[1]), "r"(a[2]), "r"(a[3]), "r"(b[0]), "r"(b[1]));
}

// ---------------- tf32 tensor-core GEMM: C = A@B (+bias) (+Cin) ----------------
// A: M x K row-major (lda), B: K x N row-major (ldb).
// Requires: M % BM == 0, K % BK == 0, lda/ldb % 4 == 0. N edge guarded.
template<int BM, int BN, int BK, int WM, int WN>
__global__ void gemm_tf32_k(int M, int N, int K,
                            const float* __restrict__ A, int lda,
                            const float* __restrict__ B, int ldb,
                            const float* __restrict__ bias,
                            const float* __restrict__ Cin, int ldcin,
                            float* __restrict__ C, int ldc)
{
    constexpr int WARPS_M = BM / WM;
    constexpr int WARPS_N = BN / WN;
    constexpr int NWARP = WARPS_M * WARPS_N;
    constexpr int NT = NWARP * 32;
    constexpr int MI = WM / 16;
    constexpr int NI = WN / 8;
    constexpr int LDA_S = BK + 4;   // As[BM][BK+4]  -> conflict-free a-frag loads
    constexpr int LDB_S = BN + 8;   // Bs[BK][BN+8]  -> conflict-free b-frag loads

    __shared__ __align__(16) uint32_t As[BM * LDA_S];
    __shared__ __align__(16) uint32_t Bs[BK * LDB_S];

    const int tid  = threadIdx.x;
    const int warp = tid >> 5;
    const int lane = tid & 31;
    const int g    = lane >> 2;
    const int t4   = lane & 3;
    const int wm   = (warp / WARPS_N) * WM;
    const int wn   = (warp % WARPS_N) * WN;
    const int bm0  = blockIdx.y * BM;
    const int bn0  = blockIdx.x * BN;

    float acc[MI][NI][4];
#pragma unroll
    for (int i = 0; i < MI; i++)
#pragma unroll
        for (int j = 0; j < NI; j++)
#pragma unroll
            for (int q = 0; q < 4; q++) acc[i][j][q] = 0.f;

    for (int k0 = 0; k0 < K; k0 += BK) {
        // ---- fill A tile (BM x BK) ----
        constexpr int A4 = BM * BK / 4;
#pragma unroll
        for (int i = tid; i < A4; i += NT) {
            int idx = i * 4;
            int m   = idx / BK;
            int kk  = idx % BK;
            float4 v = *reinterpret_cast<const float4*>(
                &A[(size_t)(bm0 + m) * lda + k0 + kk]);
            uint4 u;
            u.x = f2tf(v.x); u.y = f2tf(v.y); u.z = f2tf(v.z); u.w = f2tf(v.w);
            *reinterpret_cast<uint4*>(&As[m * LDA_S + kk]) = u;
        }
        // ---- fill B tile (BK x BN) ----
        constexpr int B4 = BK * BN / 4;
#pragma unroll
        for (int i = tid; i < B4; i += NT) {
            int idx = i * 4;
            int kk  = idx / BN;
            int nn  = idx % BN;
            int col = bn0 + nn;
            float4 v;
            if (col + 3 < N) {
                v = *reinterpret_cast<const float4*>(
                    &B[(size_t)(k0 + kk) * ldb + col]);
            } else {
                v.x = (col + 0 < N) ? B[(size_t)(k0 + kk) * ldb + col + 0] : 0.f;
                v.y = (col + 1 < N) ? B[(size_t)(k0 + kk) * ldb + col + 1] : 0.f;
                v.z = (col + 2 < N) ? B[(size_t)(k0 + kk) * ldb + col + 2] : 0.f;
                v.w = (col + 3 < N) ? B[(size_t)(k0 + kk) * ldb + col + 3] : 0.f;
            }
            uint4 u;
            u.x = f2tf(v.x); u.y = f2tf(v.y); u.z = f2tf(v.z); u.w = f2tf(v.w);
            *reinterpret_cast<uint4*>(&Bs[kk * LDB_S + nn]) = u;
        }
        __syncthreads();

#pragma unroll
        for (int ks = 0; ks < BK; ks += 8) {
            uint32_t af[MI][4];
            uint32_t bf[NI][2];
#pragma unroll
            for (int mi = 0; mi < MI; mi++) {
                int mb = wm + mi * 16;
                af[mi][0] = As[(mb + g)     * LDA_S + ks + t4];
                af[mi][1] = As[(mb + g + 8) * LDA_S + ks + t4];
                af[mi][2] = As[(mb + g)     * LDA_S + ks + t4 + 4];
                af[mi][3] = As[(mb + g + 8) * LDA_S + ks + t4 + 4];
            }
#pragma unroll
            for (int ni = 0; ni < NI; ni++) {
                int nb = wn + ni * 8;
                bf[ni][0] = Bs[(ks + t4)     * LDB_S + nb + g];
                bf[ni][1] = Bs[(ks + t4 + 4) * LDB_S + nb + g];
            }
#pragma unroll
            for (int mi = 0; mi < MI; mi++)
#pragma unroll
                for (int ni = 0; ni < NI; ni++)
                    mma_tf32(acc[mi][ni], af[mi], bf[ni]);
        }
        __syncthreads();
    }

    // ---- epilogue ----
#pragma unroll
    for (int mi = 0; mi < MI; mi++) {
#pragma unroll
        for (int ni = 0; ni < NI; ni++) {
            int r0 = bm0 + wm + mi * 16 + g;
            int r1 = r0 + 8;
            int c0 = bn0 + wn + ni * 8 + 2 * t4;
#pragma unroll
            for (int half = 0; half < 2; half++) {
                int r = half ? r1 : r0;
                float v0 = acc[mi][ni][half * 2 + 0];
                float v1 = acc[mi][ni][half * 2 + 1];
                if (c0 < N) {
                    float w0 = v0;
                    if (bias) w0 += bias[c0];
                    if (Cin)  w0 += Cin[(size_t)r * ldcin + c0];
                    C[(size_t)r * ldc + c0] = w0;
                }
                if (c0 + 1 < N) {
                    float w1 = v1;
                    if (bias) w1 += bias[c0 + 1];
                    if (Cin)  w1 += Cin[(size_t)r * ldcin + c0 + 1];
                    C[(size_t)r * ldc + c0 + 1] = w1;
                }
            }
        }
    }
}

// ---------------- small kernels ----------------
__global__ void transpose_images_k(const float* __restrict__ images)
{
    int idx = blockIdx.x * blockDim.x + threadIdx.x;
    if (idx >= 2048 * CIN) return;
    int m = idx / CIN;
    int c = idx % CIN;
    int n = m >> 4;
    int p = m & 15;
    g_imgT[idx] = images[((size_t)n * CIN + c) * 16 + p];
}

__global__ void h0_k()
{
    int idx = blockIdx.x * blockDim.x + threadIdx.x;
    if (idx >= NB * HD) return;
    int n = idx / HD;
    int h = idx % HD;
    float s = 0.f;
#pragma unroll
    for (int p = 0; p < 16; p++)
        s += g_A2[((size_t)n * 16 + p) * HD + h];
    s *= (1.f / 16.f);
    g_hcat[n * K2 + h] = s;
    g_c[idx] = s;
}

__global__ void build_wcat_k(const float* __restrict__ Wh,
                             const float* __restrict__ Wattn)
{
    int idx = blockIdx.x * blockDim.x + threadIdx.x;
    if (idx >= K2 * G4) return;
    int r = idx / G4;
    int j = idx % G4;
    g_Wcat[idx] = (r < HD) ? Wh[(size_t)r * G4 + j]
                           : Wattn[(size_t)(r - HD) * G4 + j];
}

__global__ void embed_k(const int* __restrict__ caps,
                        const float* __restrict__ W_embed)
{
    int idx = blockIdx.x * blockDim.x + threadIdx.x;
    if (idx >= NB * TT * WD) return;
    int row = idx / WD;
    int d   = idx % WD;
    int n = row / TT;
    int t = row % TT;
    int tok = caps[n * TCAP + t];
    g_xemb[idx] = W_embed[(size_t)tok * WD + d];
}

// initial attention (from h0): scores -> softmax(16) -> attn
__global__ void attn_k()
{
    const int n = blockIdx.x;
    const float* __restrict__ h  = g_hcat + (size_t)n * K2;
    const float* __restrict__ An = g_A2 + (size_t)n * 16 * HD;

    __shared__ float sc[16];
    __shared__ float w[16];

    int wid  = threadIdx.x >> 5;
    int lane = threadIdx.x & 31;

    float s = 0.f;
    for (int hh = lane; hh < HD; hh += 32)
        s += h[hh] * An[wid * HD + hh];
#pragma unroll
    for (int o = 16; o; o >>= 1)
        s += __shfl_xor_sync(0xFFFFFFFFu, s, o);
    if (lane == 0) sc[wid] = s * 0.03125f;
    __syncthreads();

    if (threadIdx.x == 0) {
        float mx = sc[0];
#pragma unroll
        for (int p = 1; p < 16; p++) mx = fmaxf(mx, sc[p]);
        float se = 0.f;
#pragma unroll
        for (int p = 0; p < 16; p++) { float e = expf(sc[p] - mx); w[p] = e; se += e; }
        float inv = 1.f / se;
#pragma unroll
        for (int p = 0; p < 16; p++) w[p] *= inv;
    }
    __syncthreads();

    for (int hh = threadIdx.x; hh < HD; hh += 512) {
        float acc = 0.f;
#pragma unroll
        for (int p = 0; p < 16; p++)
            acc += w[p] * An[p * HD + hh];
        g_hcat[(size_t)n * K2 + HD + hh] = acc;
    }
}

__device__ __forceinline__ float sigf(float x) { return 1.f / (1.f + expf(-x)); }

// fused LSTM elementwise + attention for the NEXT step. One block per batch n.
__global__ void lstm_attn_k(int t)
{
    const int n = blockIdx.x;
    const float* __restrict__ an = g_a + (size_t)n * G4;
    const float* __restrict__ An = g_A2 + (size_t)n * 16 * HD;

    __shared__ float hsm[HD];
    __shared__ float sc[16];
    __shared__ float w[16];

    // LSTM elementwise
    for (int h = threadIdx.x; h < HD; h += 512) {
        float i_ = an[h];
        float f_ = an[HD + h];
        float o_ = an[2 * HD + h];
        float gg = an[3 * HD + h];
        float cp = g_c[n * HD + h];
        float cn = sigf(f_) * cp + sigf(i_) * tanhf(gg);
        float hn = sigf(o_) * tanhf(cn);
        g_c[n * HD + h] = cn;
        hsm[h] = hn;
        g_hcat[(size_t)n * K2 + h] = hn;
        g_hs[((size_t)n * TT + t) * HD + h] = hn;
    }
    __syncthreads();

    // attention scores (16 warps, one pixel each)
    int wid  = threadIdx.x >> 5;
    int lane = threadIdx.x & 31;
    float s = 0.f;
    for (int hh = lane; hh < HD; hh += 32)
        s += hsm[hh] * An[wid * HD + hh];
#pragma unroll
    for (int o = 16; o; o >>= 1)
        s += __shfl_xor_sync(0xFFFFFFFFu, s, o);
    if (lane == 0) sc[wid] = s * 0.03125f;
    __syncthreads();

    if (threadIdx.x == 0) {
        float mx = sc[0];
#pragma unroll
        for (int p = 1; p < 16; p++) mx = fmaxf(mx, sc[p]);
        float se = 0.f;
#pragma unroll
        for (int p = 0; p < 16; p++) { float e = expf(sc[p] - mx); w[p] = e; se += e; }
        float inv = 1.f / se;
#pragma unroll
        for (int p = 0; p < 16; p++) w[p] *= inv;
    }
    __syncthreads();

    for (int hh = threadIdx.x; hh < HD; hh += 512) {
        float acc = 0.f;
#pragma unroll
        for (int p = 0; p < 16; p++)
            acc += w[p] * An[p * HD + hh];
        g_hcat[(size_t)n * K2 + HD + hh] = acc;
    }
}

__global__ void loss_row_k(const int* __restrict__ caps)
{
    const int r = blockIdx.x;
    const int n = r / TT;
    const int t = r % TT;
    const int tgt = caps[n * TCAP + t + 1];
    const float* __restrict__ L = g_logits + (size_t)r * VO;

    __shared__ float red[256];
    const int tid = threadIdx.x;

    float mx = -1e30f;
    for (int j = tid; j < VO; j += 256) mx = fmaxf(mx, L[j]);
    red[tid] = mx; __syncthreads();
    for (int s = 128; s; s >>= 1) {
        if (tid < s) red[tid] = fmaxf(red[tid], red[tid + s]);
        __syncthreads();
    }
    mx = red[0]; __syncthreads();

    float se = 0.f;
    for (int j = tid; j < VO; j += 256) se += expf(L[j] - mx);
    red[tid] = se; __syncthreads();
    for (int s = 128; s; s >>= 1) {
        if (tid < s) red[tid] += red[tid + s];
        __syncthreads();
    }
    if (tid == 0) {
        float lse = mx + logf(red[0]);
        float nll = lse - L[tgt];
        g_rowloss[r] = (tgt != 0) ? nll : 0.f;
    }
}

__global__ void final_k(float* __restrict__ out)
{
    __shared__ float red[256];
    const int tid = threadIdx.x;
    float s = 0.f;
    for (int r = tid; r < NB * TT; r += 256) s += g_rowloss[r];
    red[tid] = s; __syncthreads();
    for (int st = 128; st; st >>= 1) {
        if (tid < st) red[tid] += red[tid + st];
        __syncthreads();
    }
    if (tid == 0) out[0] = red[0] / (float)NB;
}

// ---------------- launch ----------------
extern "C" void kernel_launch(void* const* d_in, const int* in_sizes, int n_in,
                              void* d_out, int out_size)
{
    const float* images  = (const float*)d_in[0];
    const int*   caps    = (const int*)  d_in[1];
    const float* W_embed = (const float*)d_in[2];
    const float* W_proj  = (const float*)d_in[3];
    const float* b_proj  = (const float*)d_in[4];
    const float* Wx      = (const float*)d_in[5];
    const float* Wh      = (const float*)d_in[6];
    const float* Wattn   = (const float*)d_in[7];
    const float* b       = (const float*)d_in[8];
    const float* W_vocab = (const float*)d_in[9];
    const float* b_vocab = (const float*)d_in[10];
    float* out = (float*)d_out;

    static float *p_imgT = nullptr, *p_A2, *p_hcat, *p_Wcat, *p_xemb,
                 *p_xpre, *p_a, *p_hs, *p_logits;
    if (!p_imgT) {
        cudaGetSymbolAddress((void**)&p_imgT,   g_imgT);
        cudaGetSymbolAddress((void**)&p_A2,     g_A2);
        cudaGetSymbolAddress((void**)&p_hcat,   g_hcat);
        cudaGetSymbolAddress((void**)&p_Wcat,   g_Wcat);
        cudaGetSymbolAddress((void**)&p_xemb,   g_xemb);
        cudaGetSymbolAddress((void**)&p_xpre,   g_xpre);
        cudaGetSymbolAddress((void**)&p_a,      g_a);
        cudaGetSymbolAddress((void**)&p_hs,     g_hs);
        cudaGetSymbolAddress((void**)&p_logits, g_logits);
    }

    // 1. transpose images -> (n*16+p, c)
    transpose_images_k<<<(2048 * CIN + 255) / 256, 256>>>(images);

    // 2. projection: A2 (2048 x 1024) = imgT @ W_proj + b_proj
    gemm_tf32_k<128, 128, 32, 64, 32><<<dim3(HD / 128, 2048 / 128), 256>>>(
        2048, HD, CIN, p_imgT, CIN, W_proj, HD, b_proj, nullptr, 0, p_A2, HD);

    // 3. h0 = mean over pixels
    h0_k<<<(NB * HD + 255) / 256, 256>>>();

    // 4. Wcat = [Wh ; Wattn]
    build_wcat_k<<<(K2 * G4 + 255) / 256, 256>>>(Wh, Wattn);

    // 5. embedding gather
    embed_k<<<(NB * TT * WD + 255) / 256, 256>>>(caps, W_embed);

    // 6. x_pre = x_emb @ Wx + b
    gemm_tf32_k<128, 128, 32, 64, 32><<<dim3(G4 / 128, (NB * TT) / 128), 256>>>(
        NB * TT, G4, WD, p_xemb, WD, Wx, G4, b, nullptr, 0, p_xpre, G4);

    // 7. initial attention from h0
    attn_k<<<NB, 512>>>();

    // 8. recurrent loop: step GEMM + fused lstm/attn
    for (int t = 0; t < TT; t++) {
        gemm_tf32_k<64, 64, 32, 32, 32><<<dim3(G4 / 64, NB / 64), 128>>>(
            NB, G4, K2, p_hcat, K2, p_Wcat, G4,
            nullptr, p_xpre + (size_t)t * G4, TT * G4, p_a, G4);
        lstm_attn_k<<<NB, 512>>>(t);
    }

    // 9. logits = hs @ W_vocab + b_vocab
    gemm_tf32_k<128, 128, 32, 64, 32><<<dim3((VO + 127) / 128, (NB * TT) / 128), 256>>>(
        NB * TT, VO, HD, p_hs, HD, W_vocab, VO, b_vocab, nullptr, 0, p_logits, VO);

    // 10. per-row logsumexp + masked NLL
    loss_row_k<<<NB * TT, 256>>>(caps);

    // 11. final masked mean
    final_k<<<1, 256>>>(out);
}

// round 4
// speedup vs baseline: 5.7848x; 4.9027x over previous
#include <cuda_runtime.h>
#include <cuda_bf16.h>
#include <math.h>
#include <stdint.h>

// Problem constants
#define NB   128
#define TT   30
#define TCAP 31
#define CIN  1280
#define WD   512
#define HD   1024
#define VO   10000
#define G4   4096
#define K2   2048
#define NP   316          // vocab loss partials per row = 79 col-blocks * 4 warp_n
#define NPS  320          // partial stride

typedef __nv_bfloat16 bf16;

// ---------------- device scratch (allocation-free) ----------------
__device__ __align__(16) bf16  g_imgT[2048 * CIN];       // (n*16+p, c)  bf16
__device__ __align__(16) float g_A2[2048 * HD];          // fp32 (attention needs it)
__device__ __align__(16) bf16  g_hcat[NB * K2];          // [h | attn] bf16
__device__ __align__(16) float g_c[NB * HD];
__device__ __align__(16) bf16  g_Wcat[K2 * G4];          // [Wh ; Wattn] bf16
__device__ __align__(16) bf16  g_Wproj[CIN * HD];
__device__ __align__(16) bf16  g_Wx[WD * G4];
__device__ __align__(16) bf16  g_Wvocab[(size_t)HD * VO];
__device__ __align__(16) bf16  g_xemb[NB * TT * WD];
__device__ __align__(16) float g_xpre[NB * TT * G4];     // fp32 (Cin for step gemm)
__device__ __align__(16) float g_a[NB * G4];
__device__ __align__(16) bf16  g_hs[NB * TT * HD];
__device__ __align__(16) float g_pmax[(size_t)NB * TT * NPS];
__device__ __align__(16) float g_psum[(size_t)NB * TT * NPS];
__device__ __align__(16) float g_tgtlogit[NB * TT];
__device__ __align__(16) float g_rowloss[NB * TT];

// ---------------- ptx helpers ----------------
__device__ __forceinline__ void cpa16(uint32_t dst, const void* src, bool pred) {
    int sz = pred ? 16 : 0;
    asm volatile("cp.async.cg.shared.global [%0], [%1], 16, %2;\n"
                 :: "r"(dst), "l"(src), "r"(sz));
}
__device__ __forceinline__ void cpcommit() { asm volatile("cp.async.commit_group;\n"); }
template<int W> __device__ __forceinline__ void cpwait() {
    asm volatile("cp.async.wait_group %0;\n" :: "n"(W));
}
__device__ __forceinline__ void ldsm_x4(uint32_t r[4], uint32_t saddr) {
    asm volatile("ldmatrix.sync.aligned.m8n8.x4.shared.b16 {%0,%1,%2,%3}, [%4];\n"
                 : "=r"(r[0]), "=r"(r[1]), "=r"(r[2]), "=r"(r[3]) : "r"(saddr));
}
__device__ __forceinline__ void ldsm_x4_t(uint32_t r[4], uint32_t saddr) {
    asm volatile("ldmatrix.sync.aligned.m8n8.x4.trans.shared.b16 {%0,%1,%2,%3}, [%4];\n"
                 : "=r"(r[0]), "=r"(r[1]), "=r"(r[2]), "=r"(r[3]) : "r"(saddr));
}
__device__ __forceinline__ void mma_bf16(float c[4], const uint32_t a[4], const uint32_t b[2]) {
    asm volatile(
        "mma.sync.aligned.m16n8k16.row.col.f32.bf16.bf16.f32 "
        "{%0,%1,%2,%3}, {%4,%5,%6,%7}, {%8,%9}, {%0,%1,%2,%3};\n"
        : "+f"(c[0]), "+f"(c[1]), "+f"(c[2]), "+f"(c[3])
        : "r"(a[0]), "r"(a[1]), "r"(a[2]), "r"(a[3]), "r"(b[0]), "r"(b[1]));
}

// ---------------- bf16 tensor-core GEMM ----------------
// C(fp32) = A(bf16) @ B(bf16) (+bias) (+Cin). A: MxK rm, B: KxN rm.
// Requires M%BM==0, K%BK==0, lda/ldb%8==0. B column edge zero-filled.
// LOSS: no C write; per-warp-tile (max, sumexp) partials + target logit.
// Thread count MUST be (BM/WM)*(BN/WN)*32.
template<int BM, int BN, int BK, int WM, int WN, bool LOSS>
__global__ __launch_bounds__((BM/WM)*(BN/WN)*32)
void gemm_bf16_k(int M, int N, int K,
                 const bf16* __restrict__ A, int lda,
                 const bf16* __restrict__ B, int ldb,
                 const float* __restrict__ bias,
                 const float* __restrict__ Cin, int ldcin,
                 float* __restrict__ C, int ldc,
                 const int* __restrict__ caps)
{
    constexpr int WARPS_M = BM / WM;
    constexpr int WARPS_N = BN / WN;
    constexpr int NT = WARPS_M * WARPS_N * 32;
    constexpr int MI = WM / 16;
    constexpr int NI = WN / 8;
    constexpr int SA = BK + 8;          // bf16 elements per A row (pad 8)
    constexpr int SB = BN + 8;          // bf16 elements per B row (pad 8)
    constexpr int BKC = BK / 8;         // 16B chunks per A row
    constexpr int BNC = BN / 8;         // 16B chunks per B row

    __shared__ __align__(32) bf16 As[2 * BM * SA];
    __shared__ __align__(32) bf16 Bs[2 * BK * SB];

    const int tid  = threadIdx.x;
    const int warp = tid >> 5;
    const int lane = tid & 31;
    const int g    = lane >> 2;
    const int t4   = lane & 3;
    const int wm   = (warp / WARPS_N) * WM;
    const int wn   = (warp % WARPS_N) * WN;
    const int bm0  = blockIdx.y * BM;
    const int bn0  = blockIdx.x * BN;

    const uint32_t as_u = (uint32_t)__cvta_generic_to_shared(As);
    const uint32_t bs_u = (uint32_t)__cvta_generic_to_shared(Bs);

    float acc[MI][NI][4];
#pragma unroll
    for (int i = 0; i < MI; i++)
#pragma unroll
        for (int j = 0; j < NI; j++)
#pragma unroll
            for (int q = 0; q < 4; q++) acc[i][j][q] = 0.f;

    auto fill = [&](int st, int k0) {
        uint32_t ab = as_u + st * (BM * SA * 2);
#pragma unroll
        for (int i = tid; i < BM * BKC; i += NT) {
            int m  = i / BKC;
            int kc = i % BKC;
            cpa16(ab + (m * SA + kc * 8) * 2,
                  A + (size_t)(bm0 + m) * lda + k0 + kc * 8, true);
        }
        uint32_t bb = bs_u + st * (BK * SB * 2);
#pragma unroll
        for (int i = tid; i < BK * BNC; i += NT) {
            int kk = i / BNC;
            int nc = i % BNC;
            int col = bn0 + nc * 8;
            cpa16(bb + (kk * SB + nc * 8) * 2,
                  B + (size_t)(k0 + kk) * ldb + col, col + 8 <= N);
        }
        cpcommit();
    };

    auto compute = [&](int st) {
        uint32_t ab = as_u + st * (BM * SA * 2);
        uint32_t bb = bs_u + st * (BK * SB * 2);
#pragma unroll
        for (int ks = 0; ks < BK; ks += 16) {
            uint32_t af[MI][4];
            uint32_t bfr[NI][2];
#pragma unroll
            for (int mi = 0; mi < MI; mi++) {
                int row = wm + mi * 16 + (lane & 15);
                int col = ks + ((lane >> 4) << 3);
                ldsm_x4(af[mi], ab + (row * SA + col) * 2);
            }
#pragma unroll
            for (int ni = 0; ni < NI; ni += 2) {
                int krow = ks + (lane & 15);
                int col  = wn + ni * 8 + ((lane >> 4) << 3);
                uint32_t r4[4];
                ldsm_x4_t(r4, bb + (krow * SB + col) * 2);
                bfr[ni][0] = r4[0]; bfr[ni][1] = r4[1];
                bfr[ni + 1][0] = r4[2]; bfr[ni + 1][1] = r4[3];
            }
#pragma unroll
            for (int mi = 0; mi < MI; mi++)
#pragma unroll
                for (int ni = 0; ni < NI; ni++)
                    mma_bf16(acc[mi][ni], af[mi], bfr[ni]);
        }
    };

    const int KT = K / BK;
    fill(0, 0);
    for (int kt = 0; kt < KT; kt++) {
        int st = kt & 1;
        if (kt + 1 < KT) {
            fill(st ^ 1, (kt + 1) * BK);
            cpwait<1>();
        } else {
            cpwait<0>();
        }
        __syncthreads();
        compute(st);
        __syncthreads();
    }

    if (!LOSS) {
        // all C-writing GEMMs here have N % BN == 0 -> no col guard
#pragma unroll
        for (int mi = 0; mi < MI; mi++) {
#pragma unroll
            for (int ni = 0; ni < NI; ni++) {
                int c = bn0 + wn + ni * 8 + 2 * t4;
#pragma unroll
                for (int half = 0; half < 2; half++) {
                    int r = bm0 + wm + mi * 16 + g + half * 8;
                    float v0 = acc[mi][ni][half * 2 + 0];
                    float v1 = acc[mi][ni][half * 2 + 1];
                    if (bias) { v0 += bias[c]; v1 += bias[c + 1]; }
                    if (Cin) {
                        const float* ci = &Cin[(size_t)r * ldcin + c];
                        v0 += ci[0]; v1 += ci[1];
                    }
                    float2 o; o.x = v0; o.y = v1;
                    *reinterpret_cast<float2*>(&C[(size_t)r * ldc + c]) = o;
                }
            }
        }
    } else {
        const int wn_idx = warp % WARPS_N;
        const int pidx = blockIdx.x * WARPS_N + wn_idx;
#pragma unroll
        for (int mi = 0; mi < MI; mi++) {
#pragma unroll
            for (int half = 0; half < 2; half++) {
                int r = bm0 + wm + mi * 16 + g + half * 8;
                int nn = r / TT, t = r % TT;
                int tg = caps[nn * TCAP + t + 1];
                float v[NI * 2];
                float mx = -1e30f;
#pragma unroll
                for (int ni = 0; ni < NI; ni++) {
                    int c = bn0 + wn + ni * 8 + 2 * t4;
                    float a0 = acc[mi][ni][half * 2 + 0];
                    float a1 = acc[mi][ni][half * 2 + 1];
                    float w0 = (c     < N) ? a0 + bias[c]     : -1e30f;
                    float w1 = (c + 1 < N) ? a1 + bias[c + 1] : -1e30f;
                    v[2 * ni]     = w0;
                    v[2 * ni + 1] = w1;
                    if (c     == tg) g_tgtlogit[r] = w0;
                    if (c + 1 == tg) g_tgtlogit[r] = w1;
                    mx = fmaxf(mx, fmaxf(w0, w1));
                }
                // quad reduce (lanes 4g..4g+3 share row r)
                mx = fmaxf(mx, __shfl_xor_sync(0xFFFFFFFFu, mx, 1));
                mx = fmaxf(mx, __shfl_xor_sync(0xFFFFFFFFu, mx, 2));
                float s = 0.f;
#pragma unroll
                for (int i = 0; i < NI * 2; i++) s += __expf(v[i] - mx);
                s += __shfl_xor_sync(0xFFFFFFFFu, s, 1);
                s += __shfl_xor_sync(0xFFFFFFFFu, s, 2);
                if (t4 == 0) {
                    g_pmax[(size_t)r * NPS + pidx] = mx;
                    g_psum[(size_t)r * NPS + pidx] = s;
                }
            }
        }
    }
}

// ---------------- small kernels ----------------
__global__ void f2b_k(const float* __restrict__ src, bf16* __restrict__ dst, int n4)
{
    int i = blockIdx.x * blockDim.x + threadIdx.x;
    if (i >= n4) return;
    float4 v = reinterpret_cast<const float4*>(src)[i];
    __nv_bfloat162 lo = __floats2bfloat162_rn(v.x, v.y);
    __nv_bfloat162 hi = __floats2bfloat162_rn(v.z, v.w);
    reinterpret_cast<__nv_bfloat162*>(dst)[2 * i]     = lo;
    reinterpret_cast<__nv_bfloat162*>(dst)[2 * i + 1] = hi;
}

__global__ void transpose_images_k(const float* __restrict__ images)
{
    int idx = blockIdx.x * blockDim.x + threadIdx.x;
    if (idx >= 2048 * CIN) return;
    int m = idx / CIN;
    int c = idx % CIN;
    int n = m >> 4;
    int p = m & 15;
    g_imgT[idx] = __float2bfloat16_rn(images[((size_t)n * CIN + c) * 16 + p]);
}

__global__ void h0_k()
{
    int idx = blockIdx.x * blockDim.x + threadIdx.x;
    if (idx >= NB * HD) return;
    int n = idx / HD;
    int h = idx % HD;
    float s = 0.f;
#pragma unroll
    for (int p = 0; p < 16; p++)
        s += g_A2[((size_t)n * 16 + p) * HD + h];
    s *= (1.f / 16.f);
    g_hcat[n * K2 + h] = __float2bfloat16_rn(s);
    g_c[idx] = s;                        // c0 == h0 (also used by attn0 as fp32 h)
}

__global__ void build_wcat_k(const float* __restrict__ Wh,
                             const float* __restrict__ Wattn)
{
    int idx = blockIdx.x * blockDim.x + threadIdx.x;
    if (idx >= K2 * G4) return;
    int r = idx / G4;
    int j = idx % G4;
    float v = (r < HD) ? Wh[(size_t)r * G4 + j] : Wattn[(size_t)(r - HD) * G4 + j];
    g_Wcat[idx] = __float2bfloat16_rn(v);
}

__global__ void embed_k(const int* __restrict__ caps,
                        const float* __restrict__ W_embed)
{
    int idx = blockIdx.x * blockDim.x + threadIdx.x;
    if (idx >= NB * TT * WD) return;
    int row = idx / WD;
    int d   = idx % WD;
    int n = row / TT;
    int t = row % TT;
    int tok = caps[n * TCAP + t];
    g_xemb[idx] = __float2bfloat16_rn(W_embed[(size_t)tok * WD + d]);
}

// initial attention from h0 (fp32 h0 lives in g_c)
__global__ void attn0_k()
{
    const int n = blockIdx.x;
    const float* __restrict__ h  = g_c + (size_t)n * HD;
    const float* __restrict__ An = g_A2 + (size_t)n * 16 * HD;

    __shared__ float sc[16];
    __shared__ float w[16];

    int wid  = threadIdx.x >> 5;
    int lane = threadIdx.x & 31;

    float s = 0.f;
    for (int hh = lane; hh < HD; hh += 32)
        s += h[hh] * An[wid * HD + hh];
#pragma unroll
    for (int o = 16; o; o >>= 1)
        s += __shfl_xor_sync(0xFFFFFFFFu, s, o);
    if (lane == 0) sc[wid] = s * 0.03125f;
    __syncthreads();

    if (threadIdx.x == 0) {
        float mx = sc[0];
#pragma unroll
        for (int p = 1; p < 16; p++) mx = fmaxf(mx, sc[p]);
        float se = 0.f;
#pragma unroll
        for (int p = 0; p < 16; p++) { float e = expf(sc[p] - mx); w[p] = e; se += e; }
        float inv = 1.f / se;
#pragma unroll
        for (int p = 0; p < 16; p++) w[p] *= inv;
    }
    __syncthreads();

    for (int hh = threadIdx.x; hh < HD; hh += 512) {
        float acc = 0.f;
#pragma unroll
        for (int p = 0; p < 16; p++)
            acc += w[p] * An[p * HD + hh];
        g_hcat[(size_t)n * K2 + HD + hh] = __float2bfloat16_rn(acc);
    }
}

__device__ __forceinline__ float sigf(float x) { return 1.f / (1.f + expf(-x)); }

// fused LSTM elementwise + next-step attention. One block per batch n.
__global__ void lstm_attn_k(int t)
{
    const int n = blockIdx.x;
    const float* __restrict__ an = g_a + (size_t)n * G4;
    const float* __restrict__ An = g_A2 + (size_t)n * 16 * HD;

    __shared__ float hsm[HD];
    __shared__ float sc[16];
    __shared__ float w[16];

    for (int h = threadIdx.x; h < HD; h += 512) {
        float i_ = an[h];
        float f_ = an[HD + h];
        float o_ = an[2 * HD + h];
        float gg = an[3 * HD + h];
        float cp = g_c[n * HD + h];
        float cn = sigf(f_) * cp + sigf(i_) * tanhf(gg);
        float hn = sigf(o_) * tanhf(cn);
        g_c[n * HD + h] = cn;
        hsm[h] = hn;
        bf16 hb = __float2bfloat16_rn(hn);
        g_hcat[(size_t)n * K2 + h] = hb;
        g_hs[((size_t)n * TT + t) * HD + h] = hb;
    }
    __syncthreads();

    int wid  = threadIdx.x >> 5;
    int lane = threadIdx.x & 31;
    float s = 0.f;
    for (int hh = lane; hh < HD; hh += 32)
        s += hsm[hh] * An[wid * HD + hh];
#pragma unroll
    for (int o = 16; o; o >>= 1)
        s += __shfl_xor_sync(0xFFFFFFFFu, s, o);
    if (lane == 0) sc[wid] = s * 0.03125f;
    __syncthreads();

    if (threadIdx.x == 0) {
        float mx = sc[0];
#pragma unroll
        for (int p = 1; p < 16; p++) mx = fmaxf(mx, sc[p]);
        float se = 0.f;
#pragma unroll
        for (int p = 0; p < 16; p++) { float e = expf(sc[p] - mx); w[p] = e; se += e; }
        float inv = 1.f / se;
#pragma unroll
        for (int p = 0; p < 16; p++) w[p] *= inv;
    }
    __syncthreads();

    for (int hh = threadIdx.x; hh < HD; hh += 512) {
        float acc = 0.f;
#pragma unroll
        for (int p = 0; p < 16; p++)
            acc += w[p] * An[p * HD + hh];
        g_hcat[(size_t)n * K2 + HD + hh] = __float2bfloat16_rn(acc);
    }
}

// per-row logsumexp merge of partials -> masked nll
__global__ void lse_k(const int* __restrict__ caps)
{
    int r = blockIdx.x * 8 + (threadIdx.x >> 5);
    int lane = threadIdx.x & 31;
    if (r >= NB * TT) return;
    const float* pm = g_pmax + (size_t)r * NPS;
    const float* ps = g_psum + (size_t)r * NPS;

    float M = -1e30f;
    for (int i = lane; i < NP; i += 32) M = fmaxf(M, pm[i]);
#pragma unroll
    for (int o = 16; o; o >>= 1) M = fmaxf(M, __shfl_xor_sync(0xFFFFFFFFu, M, o));

    float S = 0.f;
    for (int i = lane; i < NP; i += 32) S += ps[i] * __expf(pm[i] - M);
#pragma unroll
    for (int o = 16; o; o >>= 1) S += __shfl_xor_sync(0xFFFFFFFFu, S, o);

    if (lane == 0) {
        int n = r / TT, t = r % TT;
        int tg = caps[n * TCAP + t + 1];
        float lse = M + logf(S);
        g_rowloss[r] = (tg != 0) ? (lse - g_tgtlogit[r]) : 0.f;
    }
}

__global__ void final_k(float* __restrict__ out)
{
    __shared__ float red[256];
    const int tid = threadIdx.x;
    float s = 0.f;
    for (int r = tid; r < NB * TT; r += 256) s += g_rowloss[r];
    red[tid] = s; __syncthreads();
    for (int st = 128; st; st >>= 1) {
        if (tid < st) red[tid] += red[tid + st];
        __syncthreads();
    }
    if (tid == 0) out[0] = red[0] / (float)NB;
}

// ---------------- launch ----------------
extern "C" void kernel_launch(void* const* d_in, const int* in_sizes, int n_in,
                              void* d_out, int out_size)
{
    const float* images  = (const float*)d_in[0];
    const int*   caps    = (const int*)  d_in[1];
    const float* W_embed = (const float*)d_in[2];
    const float* W_proj  = (const float*)d_in[3];
    const float* b_proj  = (const float*)d_in[4];
    const float* Wx      = (const float*)d_in[5];
    const float* Wh      = (const float*)d_in[6];
    const float* Wattn   = (const float*)d_in[7];
    const float* b       = (const float*)d_in[8];
    const float* W_vocab = (const float*)d_in[9];
    const float* b_vocab = (const float*)d_in[10];
    float* out = (float*)d_out;

    static bf16 *p_imgT = nullptr, *p_hcat, *p_Wcat, *p_Wproj, *p_Wx, *p_Wvocab,
                *p_xemb, *p_hs;
    static float *p_A2, *p_xpre, *p_a;
    if (!p_imgT) {
        cudaGetSymbolAddress((void**)&p_imgT,   g_imgT);
        cudaGetSymbolAddress((void**)&p_hcat,   g_hcat);
        cudaGetSymbolAddress((void**)&p_Wcat,   g_Wcat);
        cudaGetSymbolAddress((void**)&p_Wproj,  g_Wproj);
        cudaGetSymbolAddress((void**)&p_Wx,     g_Wx);
        cudaGetSymbolAddress((void**)&p_Wvocab, g_Wvocab);
        cudaGetSymbolAddress((void**)&p_xemb,   g_xemb);
        cudaGetSymbolAddress((void**)&p_hs,     g_hs);
        cudaGetSymbolAddress((void**)&p_A2,     g_A2);
        cudaGetSymbolAddress((void**)&p_xpre,   g_xpre);
        cudaGetSymbolAddress((void**)&p_a,      g_a);
    }

    // weight conversions (fp32 -> bf16)
    f2b_k<<<(CIN * HD / 4 + 255) / 256, 256>>>(W_proj, p_Wproj, CIN * HD / 4);
    f2b_k<<<(WD * G4 / 4 + 255) / 256, 256>>>(Wx, p_Wx, WD * G4 / 4);
    f2b_k<<<(HD * VO / 4 + 255) / 256, 256>>>(W_vocab, p_Wvocab, HD * VO / 4);
    build_wcat_k<<<(K2 * G4 + 255) / 256, 256>>>(Wh, Wattn);

    // image transpose (fp32 -> bf16, pixel-major)
    transpose_images_k<<<(2048 * CIN + 255) / 256, 256>>>(images);

    // projection: A2 (2048x1024 fp32) = imgT_bf @ Wproj_bf + b_proj  (256 threads = 8 warps)
    gemm_bf16_k<128, 128, 32, 64, 32, false><<<dim3(HD / 128, 2048 / 128), 256>>>(
        2048, HD, CIN, p_imgT, CIN, p_Wproj, HD, b_proj, nullptr, 0, p_A2, HD, nullptr);

    // h0 + embedding
    h0_k<<<(NB * HD + 255) / 256, 256>>>();
    embed_k<<<(NB * TT * WD + 255) / 256, 256>>>(caps, W_embed);

    // x_pre (fp32) = xemb_bf @ Wx_bf + b
    gemm_bf16_k<128, 128, 32, 64, 32, false><<<dim3(G4 / 128, (NB * TT) / 128), 256>>>(
        NB * TT, G4, WD, p_xemb, WD, p_Wx, G4, b, nullptr, 0, p_xpre, G4, nullptr);

    // initial attention
    attn0_k<<<NB, 512>>>();

    // recurrent loop  (step gemm: 4 warps = 128 threads)
    for (int t = 0; t < TT; t++) {
        gemm_bf16_k<64, 64, 32, 32, 32, false><<<dim3(G4 / 64, NB / 64), 128>>>(
            NB, G4, K2, p_hcat, K2, p_Wcat, G4,
            nullptr, p_xpre + (size_t)t * G4, TT * G4, p_a, G4, nullptr);
        lstm_attn_k<<<NB, 512>>>(t);
    }

    // vocab GEMM with fused loss partials (no logits buffer)
    gemm_bf16_k<128, 128, 32, 64, 32, true><<<dim3((VO + 127) / 128, (NB * TT) / 128), 256>>>(
        NB * TT, VO, HD, p_hs, HD, p_Wvocab, VO, b_vocab, nullptr, 0, nullptr, 0, caps);

    // merge partials -> rowloss -> final
    lse_k<<<(NB * TT + 7) / 8, 256>>>(caps);
    final_k<<<1, 256>>>(out);
}